// round 15
// baseline (speedup 1.0000x reference)
#include <cuda_runtime.h>
#include <math.h>
#include <stdint.h>

// Problem constants: B=8, S=1024, D=1024, H=16, hd=64
#define NB 8
#define NS 1024
#define ND 1024
#define NH 16
#define HD 64

// Scratch (allocation-free rule: __device__ globals)
__device__ float g_Q[NB * NH * NS * HD];   // [B,H,S,hd]
__device__ float g_K[NB * NH * NS * HD];
__device__ float g_V[NB * NH * NS * HD];
__device__ float g_ctx[NB * NS * ND];      // [B,S,D]

// tf32 lives in a b32 container: cvt dst must be a .b32 register.
__device__ __forceinline__ uint32_t to_tf32(float x) {
    uint32_t r;
    asm("cvt.rna.tf32.f32 %0, %1;" : "=r"(r) : "f"(x));
    return r;
}

__device__ __forceinline__ float ex2f(float x) {
    float r;
    asm("ex2.approx.f32 %0, %1;" : "=f"(r) : "f"(x));
    return r;
}

__device__ __forceinline__ void mma_tf32(float c[4], const uint32_t a[4], const uint32_t b[2]) {
    asm volatile(
        "mma.sync.aligned.m16n8k8.row.col.f32.tf32.tf32.f32 "
        "{%0,%1,%2,%3}, {%4,%5,%6,%7}, {%8,%9}, {%0,%1,%2,%3};"
        : "+f"(c[0]), "+f"(c[1]), "+f"(c[2]), "+f"(c[3])
        : "r"(a[0]), "r"(a[1]), "r"(a[2]), "r"(a[3]), "r"(b[0]), "r"(b[1]));
}

__device__ __forceinline__ void ldsm_x4(uint4& d, uint32_t saddr) {
    asm volatile("ldmatrix.sync.aligned.m8n8.x4.shared.b16 {%0,%1,%2,%3}, [%4];"
        : "=r"(d.x), "=r"(d.y), "=r"(d.z), "=r"(d.w) : "r"(saddr));
}
__device__ __forceinline__ void ldsm_x2(uint2& d, uint32_t saddr) {
    asm volatile("ldmatrix.sync.aligned.m8n8.x2.shared.b16 {%0,%1}, [%2];"
        : "=r"(d.x), "=r"(d.y) : "r"(saddr));
}

// ---------------------------------------------------------------------------
// tf32 GEMM: ldmatrix + conflict-free padded layout, double-buffered.
// 128 threads = 4 warps (2x2), warp tile 64x64 (acc 4x8 fragments).
// Raises MMA-per-L1-wavefront ~22% vs R9's 8-warp/64x32 config.
// SMEM layout unchanged: byte(ks,row,h) = ks*6176 + row*48 + h*16.
// ---------------------------------------------------------------------------
#define KSBLK_BYTES 6176                     // 386 units * 16B
#define MAT_BUF_BYTES (4 * KSBLK_BYTES)      // 24704 per matrix per buffer
#define BUF_STRIDE (2 * MAT_BUF_BYTES)       // 49408 (A then B)
#define GEMM_SMEM_BYTES (2 * BUF_STRIDE)     // 98816

template <int MODE>
__global__ __launch_bounds__(128) void gemm_tf32(
    const float* __restrict__ A, const float* __restrict__ Bw,
    const float* __restrict__ bias, float* __restrict__ out,
    int K, int N)
{
    extern __shared__ uint32_t dynsh[];
    char* smem_c = (char*)dynsh;
    const uint32_t smem_s = (uint32_t)__cvta_generic_to_shared(dynsh);

    const int tid  = threadIdx.x;
    const int lane = tid & 31;
    const int warp = tid >> 5;       // 0..3
    const int g    = lane >> 2;
    const int tig  = lane & 3;
    const int wm0 = (warp >> 1) * 64;
    const int wn0 = (warp & 1) * 64;

    const int m0 = blockIdx.y * 128;
    const int n0 = blockIdx.x * 128;

    const float* Ap = (MODE == 2) ? (const float*)g_ctx : A;

    // ---- A global loads: 8x LDG.128 per thread ----
    // row r = (tid>>3) + 16*l (l=0..7), k-quad kc = (tid&7)*4
    const int ra = tid >> 3;          // 0..15
    const int kc = (tid & 7) * 4;     // 0..28
    const float* Aldg = Ap + (size_t)(m0 + ra) * K + kc;

    // ---- B global loads: 32x LDG.32 per thread (transpose-gather) ----
    const int nB = tid;               // n column owned (0..127)
    const float* Bldg = Bw + n0 + nB;

    // ---- smem store byte offsets ----
    const int ksA = kc >> 3, hA = (kc >> 2) & 1;
    const uint32_t a_sts0 = (uint32_t)(ksA * KSBLK_BYTES + ra * 48 + hA * 16);
    // per l: + 16*l*48 = l*768
    const uint32_t b_sts0 = (uint32_t)(nB * 48);
    // per q (0..7): + (q>>1)*KSBLK + (q&1)*16

    // ---- LDSM per-lane read offsets ----
    uint32_t a_ld[4], b_ld[8];
    {
        const int rl   = ((lane >> 3) & 1) * 8 + (lane & 7);
        const int hsel = lane >> 4;
#pragma unroll
        for (int mt = 0; mt < 4; mt++)
            a_ld[mt] = (uint32_t)((wm0 + mt * 16 + rl) * 48 + hsel * 16);
        const int nl    = lane & 7;
        const int hsel2 = (lane >> 3) & 1;
#pragma unroll
        for (int nt = 0; nt < 8; nt++)
            b_ld[nt] = (uint32_t)((wn0 + nt * 8 + nl) * 48 + hsel2 * 16);
    }

    float acc[4][8][4];
#pragma unroll
    for (int mt = 0; mt < 4; mt++)
#pragma unroll
        for (int nt = 0; nt < 8; nt++)
#pragma unroll
            for (int e = 0; e < 4; e++) acc[mt][nt][e] = 0.0f;

    float4 pa[8];
    float  bv[8][4];

    // Prologue: load tile 0
#pragma unroll
    for (int l = 0; l < 8; l++) {
        pa[l] = *(const float4*)(Aldg + (size_t)(l * 16) * K);
#pragma unroll
        for (int i = 0; i < 4; i++)
            bv[l][i] = Bldg[(size_t)(4 * l + i) * N];
    }
    // Store tile 0 -> buf 0
    {
        char* ab = smem_c;
        char* bb = smem_c + MAT_BUF_BYTES;
#pragma unroll
        for (int l = 0; l < 8; l++) {
            uint4 ta;
            ta.x = to_tf32(pa[l].x); ta.y = to_tf32(pa[l].y);
            ta.z = to_tf32(pa[l].z); ta.w = to_tf32(pa[l].w);
            *(uint4*)(ab + a_sts0 + l * 768) = ta;
            uint4 tb;
            tb.x = to_tf32(bv[l][0]); tb.y = to_tf32(bv[l][1]);
            tb.z = to_tf32(bv[l][2]); tb.w = to_tf32(bv[l][3]);
            *(uint4*)(bb + b_sts0 + (l >> 1) * KSBLK_BYTES + (l & 1) * 16) = tb;
        }
    }
    __syncthreads();

    int buf = 0;
    for (int k0 = 0; k0 < K; k0 += 32) {
        const bool more = (k0 + 32 < K);
        if (more) {
#pragma unroll
            for (int l = 0; l < 8; l++) {
                pa[l] = *(const float4*)(Aldg + (size_t)(l * 16) * K + (k0 + 32));
#pragma unroll
                for (int i = 0; i < 4; i++)
                    bv[l][i] = Bldg[(size_t)(k0 + 32 + 4 * l + i) * N];
            }
        }

        const uint32_t abase = smem_s + buf * BUF_STRIDE;
        const uint32_t bbase = abase + MAT_BUF_BYTES;
#pragma unroll
        for (int ks = 0; ks < 4; ks++) {
            const uint32_t ao = abase + ks * KSBLK_BYTES;
            const uint32_t bo = bbase + ks * KSBLK_BYTES;
            uint4 afv[4];
            uint2 bfv[8];
#pragma unroll
            for (int mt = 0; mt < 4; mt++) ldsm_x4(afv[mt], ao + a_ld[mt]);
#pragma unroll
            for (int nt = 0; nt < 8; nt++) ldsm_x2(bfv[nt], bo + b_ld[nt]);
#pragma unroll
            for (int mt = 0; mt < 4; mt++) {
                const uint32_t af[4] = {afv[mt].x, afv[mt].y, afv[mt].z, afv[mt].w};
#pragma unroll
                for (int nt = 0; nt < 8; nt++) {
                    const uint32_t bf[2] = {bfv[nt].x, bfv[nt].y};
                    mma_tf32(acc[mt][nt], af, bf);
                }
            }
        }

        if (more) {
            char* ab = smem_c + (buf ^ 1) * BUF_STRIDE;
            char* bb = ab + MAT_BUF_BYTES;
#pragma unroll
            for (int l = 0; l < 8; l++) {
                uint4 ta;
                ta.x = to_tf32(pa[l].x); ta.y = to_tf32(pa[l].y);
                ta.z = to_tf32(pa[l].z); ta.w = to_tf32(pa[l].w);
                *(uint4*)(ab + a_sts0 + l * 768) = ta;
                uint4 tb;
                tb.x = to_tf32(bv[l][0]); tb.y = to_tf32(bv[l][1]);
                tb.z = to_tf32(bv[l][2]); tb.w = to_tf32(bv[l][3]);
                *(uint4*)(bb + b_sts0 + (l >> 1) * KSBLK_BYTES + (l & 1) * 16) = tb;
            }
            __syncthreads();
            buf ^= 1;
        }
    }

    // Epilogue: c-fragment (mt,nt) covers rows {r0, r0+8}, cols {c0, c0+1}
#pragma unroll
    for (int mt = 0; mt < 4; mt++) {
        const int rbase = m0 + wm0 + mt * 16 + g;
#pragma unroll
        for (int nt = 0; nt < 8; nt++) {
            const int cbase = n0 + wn0 + nt * 8 + tig * 2;
#pragma unroll
            for (int e = 0; e < 4; e++) {
                const int r = rbase + (e >> 1) * 8;
                const int c = cbase + (e & 1);
                const float val = acc[mt][nt][e] + bias[c];
                const int b = r >> 10;
                const int s = r & 1023;
                if (MODE == 0) {
                    const int h = c >> 7;
                    const int w = c & 127;
                    if (w < 64)
                        g_Q[(((size_t)(b * NH + h)) * NS + s) * HD + w] = val;
                    else
                        g_K[(((size_t)(b * NH + h)) * NS + s) * HD + (w - 64)] = val;
                } else if (MODE == 1) {
                    const int h = c >> 6;
                    const int d = c & 63;
                    g_V[(((size_t)(b * NH + h)) * NS + s) * HD + d] = val;
                } else {
                    out[(size_t)r * N + c] = val;
                }
            }
        }
    }
}

// ---------------------------------------------------------------------------
// Flash attention: R12 passing version, unchanged.
// 256 threads / 8 warps, 128 Q-rows per CTA, 64-key tiles.
// ---------------------------------------------------------------------------
#define PT_KSB 6176
#define PT_BYTES (8 * PT_KSB)                // 49408
#define ATILE_KSB 3104
#define ATILE_BYTES (8 * ATILE_KSB)          // 24832
#define KT2_OFF PT_BYTES
#define VT2_OFF (PT_BYTES + ATILE_BYTES)
#define ATTN_SMEM_BYTES (PT_BYTES + 2 * ATILE_BYTES)   // 99072

// 0.125 * log2(e): folds softmax scale AND exp->exp2 conversion into Q.
#define QSCALE 0.18033688011112042f

__global__ __launch_bounds__(256, 2) void attn_kernel()
{
    extern __shared__ uint32_t sh[];
    char* smc = (char*)sh;
    const uint32_t smem_s = (uint32_t)__cvta_generic_to_shared(sh);

    const int tid  = threadIdx.x;
    const int lane = tid & 31;
    const int warp = tid >> 5;          // 0..7
    const int g    = lane >> 2;
    const int tig  = lane & 3;
    const int wrow = warp * 16;         // warp's Q-row base (0..112)

    const int qt = blockIdx.x;          // 0..7 (128-row Q blocks)
    const int bh = blockIdx.y;          // 0..127

    const float* Qg  = g_Q + ((size_t)bh * NS + qt * 128) * HD;
    const float* Kg0 = g_K + (size_t)bh * NS * HD;
    const float* Vg0 = g_V + (size_t)bh * NS * HD;

    // Per-lane ldsm offsets (layout-relative)
    const uint32_t a_ld_lane = (uint32_t)((lane & 15) * 48 + (lane >> 4) * 16);
    const uint32_t b_ld4 = (uint32_t)(((lane >> 4) & 1) * ATILE_KSB
                                      + ((lane >> 3) & 1) * 16 + (lane & 7) * 48);

    // ---- Stage Q (scale+log2e folded), hoist fragments to registers ----
#pragma unroll
    for (int i = 0; i < 8; i++) {
        const int f   = i * 256 + tid;       // 0..2047
        const int row = f >> 4;              // 0..127
        const int d4  = (f & 15) << 2;
        float4 v = *(const float4*)(Qg + row * HD + d4);
        uint4 t;
        t.x = to_tf32(v.x * QSCALE); t.y = to_tf32(v.y * QSCALE);
        t.z = to_tf32(v.z * QSCALE); t.w = to_tf32(v.w * QSCALE);
        *(uint4*)(smc + (d4 >> 3) * PT_KSB + row * 48 + ((d4 >> 2) & 1) * 16) = t;
    }
    __syncthreads();
    uint4 qf[8];
#pragma unroll
    for (int ks = 0; ks < 8; ks++)
        ldsm_x4(qf[ks], smem_s + ks * PT_KSB + wrow * 48 + a_ld_lane);

    float oacc[8][4];
#pragma unroll
    for (int nt = 0; nt < 8; nt++)
#pragma unroll
        for (int e = 0; e < 4; e++) oacc[nt][e] = 0.0f;
    float M0 = -1e30f, M1 = -1e30f, L0 = 0.0f, L1 = 0.0f;

    for (int kt = 0; kt < 16; kt++) {
        const float* Kg = Kg0 + (size_t)kt * 64 * HD;
        const float* Vg = Vg0 + (size_t)kt * 64 * HD;
        __syncthreads();   // previous readers done (also fences Q ldsm at kt=0)

        // K tile: natural rows, conflict-free STS.128
#pragma unroll
        for (int i = 0; i < 4; i++) {
            const int f   = i * 256 + tid;   // 0..1023
            const int row = f >> 4;          // 0..63
            const int d4  = (f & 15) << 2;
            float4 kv = *(const float4*)(Kg + row * HD + d4);
            uint4 t;
            t.x = to_tf32(kv.x); t.y = to_tf32(kv.y);
            t.z = to_tf32(kv.z); t.w = to_tf32(kv.w);
            *(uint4*)(smc + KT2_OFF + (d4 >> 3) * ATILE_KSB + row * 48 + ((d4 >> 2) & 1) * 16) = t;
        }
        // V tile transposed: thread owns (d, j0..j0+3); coalesced LDG.32
#pragma unroll
        for (int i = 0; i < 4; i++) {
            const int f  = i * 256 + tid;    // 0..1023
            const int d  = f & 63;
            const int j0 = (f >> 6) * 4;     // 0..60
            uint4 t;
            t.x = to_tf32(Vg[(j0 + 0) * HD + d]);
            t.y = to_tf32(Vg[(j0 + 1) * HD + d]);
            t.z = to_tf32(Vg[(j0 + 2) * HD + d]);
            t.w = to_tf32(Vg[(j0 + 3) * HD + d]);
            *(uint4*)(smc + VT2_OFF + (j0 >> 3) * ATILE_KSB + d * 48 + ((j0 >> 2) & 1) * 16) = t;
        }
        __syncthreads();

        // ---- S = Q @ K^T (log2 domain) ----
        float sacc[8][4];
#pragma unroll
        for (int nt = 0; nt < 8; nt++)
#pragma unroll
            for (int e = 0; e < 4; e++) sacc[nt][e] = 0.0f;

#pragma unroll
        for (int ks2 = 0; ks2 < 4; ks2++) {
            const uint32_t kbase = smem_s + KT2_OFF + ks2 * 2 * ATILE_KSB;
            const uint32_t af0[4] = {qf[2 * ks2].x, qf[2 * ks2].y, qf[2 * ks2].z, qf[2 * ks2].w};
            const uint32_t af1[4] = {qf[2 * ks2 + 1].x, qf[2 * ks2 + 1].y, qf[2 * ks2 + 1].z, qf[2 * ks2 + 1].w};
#pragma unroll
            for (int nt = 0; nt < 8; nt++) {
                uint4 bk;
                ldsm_x4(bk, kbase + nt * 8 * 48 + b_ld4);
                const uint32_t bf0[2] = {bk.x, bk.y};
                const uint32_t bf1[2] = {bk.z, bk.w};
                mma_tf32(sacc[nt], af0, bf0);
                mma_tf32(sacc[nt], af1, bf1);
            }
        }

        // ---- online softmax (rows g, g+8), log2 domain ----
        float rm0 = -1e30f, rm1 = -1e30f;
#pragma unroll
        for (int nt = 0; nt < 8; nt++) {
            rm0 = fmaxf(rm0, fmaxf(sacc[nt][0], sacc[nt][1]));
            rm1 = fmaxf(rm1, fmaxf(sacc[nt][2], sacc[nt][3]));
        }
        rm0 = fmaxf(rm0, __shfl_xor_sync(0xffffffffu, rm0, 1));
        rm0 = fmaxf(rm0, __shfl_xor_sync(0xffffffffu, rm0, 2));
        rm1 = fmaxf(rm1, __shfl_xor_sync(0xffffffffu, rm1, 1));
        rm1 = fmaxf(rm1, __shfl_xor_sync(0xffffffffu, rm1, 2));

        const float mn0 = fmaxf(M0, rm0);
        const float mn1 = fmaxf(M1, rm1);
        const float fac0 = ex2f(M0 - mn0);
        const float fac1 = ex2f(M1 - mn1);
        float rs0 = 0.0f, rs1 = 0.0f;
#pragma unroll
        for (int nt = 0; nt < 8; nt++) {
            float p0 = ex2f(sacc[nt][0] - mn0);
            float p1 = ex2f(sacc[nt][1] - mn0);
            float p2 = ex2f(sacc[nt][2] - mn1);
            float p3 = ex2f(sacc[nt][3] - mn1);
            rs0 += p0 + p1;
            rs1 += p2 + p3;
            uint2 u0, u1;
            u0.x = to_tf32(p0); u0.y = to_tf32(p1);
            u1.x = to_tf32(p2); u1.y = to_tf32(p3);
            // P tile: A-layout, k = j
            *(uint2*)(smc + nt * PT_KSB + (wrow + g) * 48 + tig * 8) = u0;
            *(uint2*)(smc + nt * PT_KSB + (wrow + g + 8) * 48 + tig * 8) = u1;
        }
        rs0 += __shfl_xor_sync(0xffffffffu, rs0, 1);
        rs0 += __shfl_xor_sync(0xffffffffu, rs0, 2);
        rs1 += __shfl_xor_sync(0xffffffffu, rs1, 1);
        rs1 += __shfl_xor_sync(0xffffffffu, rs1, 2);
        L0 = L0 * fac0 + rs0;
        L1 = L1 * fac1 + rs1;
        M0 = mn0; M1 = mn1;
#pragma unroll
        for (int nt = 0; nt < 8; nt++) {
            oacc[nt][0] *= fac0; oacc[nt][1] *= fac0;
            oacc[nt][2] *= fac1; oacc[nt][3] *= fac1;
        }
        __syncwarp();     // P rows are per-warp

        // ---- O += P @ V ----
#pragma unroll
        for (int ks2 = 0; ks2 < 4; ks2++) {
            uint4 pf0, pf1;
            ldsm_x4(pf0, smem_s + (2 * ks2)     * PT_KSB + wrow * 48 + a_ld_lane);
            ldsm_x4(pf1, smem_s + (2 * ks2 + 1) * PT_KSB + wrow * 48 + a_ld_lane);
            const uint32_t pa0[4] = {pf0.x, pf0.y, pf0.z, pf0.w};
            const uint32_t pa1[4] = {pf1.x, pf1.y, pf1.z, pf1.w};
            const uint32_t vbase = smem_s + VT2_OFF + ks2 * 2 * ATILE_KSB;
#pragma unroll
            for (int nt = 0; nt < 8; nt++) {
                uint4 bvv;
                ldsm_x4(bvv, vbase + nt * 8 * 48 + b_ld4);
                const uint32_t bf0[2] = {bvv.x, bvv.y};
                const uint32_t bf1[2] = {bvv.z, bvv.w};
                mma_tf32(oacc[nt], pa0, bf0);
                mma_tf32(oacc[nt], pa1, bf1);
            }
        }
        __syncwarp();     // done reading P before next overwrite
    }

    // Finalize: divide by L, write ctx [B,S,D]  (D col = h*64 + d)
    const int b = bh >> 4;
    const int h = bh & 15;
    const float inv0 = 1.0f / L0;
    const float inv1 = 1.0f / L1;
    const int sr0 = qt * 128 + wrow + g;
    float* out0 = g_ctx + ((size_t)(b * NS + sr0))     * ND + h * HD;
    float* out1 = g_ctx + ((size_t)(b * NS + sr0 + 8)) * ND + h * HD;
#pragma unroll
    for (int nt = 0; nt < 8; nt++) {
        const int c = nt * 8 + 2 * tig;
        *(float2*)(out0 + c) = make_float2(oacc[nt][0] * inv0, oacc[nt][1] * inv0);
        *(float2*)(out1 + c) = make_float2(oacc[nt][2] * inv1, oacc[nt][3] * inv1);
    }
}

// ---------------------------------------------------------------------------
extern "C" void kernel_launch(void* const* d_in, const int* in_sizes, int n_in,
                              void* d_out, int out_size)
{
    const float* in_q = (const float*)d_in[0];
    const float* enc  = (const float*)d_in[1];
    const float* Wqk  = (const float*)d_in[2];
    const float* bqk  = (const float*)d_in[3];
    const float* Wv   = (const float*)d_in[4];
    const float* bv   = (const float*)d_in[5];
    const float* Wo   = (const float*)d_in[6];
    const float* bo   = (const float*)d_in[7];
    float* out = (float*)d_out;

    cudaFuncSetAttribute(gemm_tf32<0>,
                         cudaFuncAttributeMaxDynamicSharedMemorySize,
                         GEMM_SMEM_BYTES);
    cudaFuncSetAttribute(gemm_tf32<1>,
                         cudaFuncAttributeMaxDynamicSharedMemorySize,
                         GEMM_SMEM_BYTES);
    cudaFuncSetAttribute(gemm_tf32<2>,
                         cudaFuncAttributeMaxDynamicSharedMemorySize,
                         GEMM_SMEM_BYTES);
    cudaFuncSetAttribute(attn_kernel,
                         cudaFuncAttributeMaxDynamicSharedMemorySize,
                         ATTN_SMEM_BYTES);

    gemm_tf32<0><<<dim3(2048 / 128, 8192 / 128), 128, GEMM_SMEM_BYTES>>>(enc, Wqk, bqk, nullptr, 1024, 2048);
    gemm_tf32<1><<<dim3(1024 / 128, 8192 / 128), 128, GEMM_SMEM_BYTES>>>(in_q, Wv, bv, nullptr, 1024, 1024);
    attn_kernel<<<dim3(8, 128), 256, ATTN_SMEM_BYTES>>>();
    gemm_tf32<2><<<dim3(1024 / 128, 8192 / 128), 128, GEMM_SMEM_BYTES>>>(nullptr, Wo, bo, out, 1024, 1024);
}